// round 6
// baseline (speedup 1.0000x reference)
#include <cuda_runtime.h>
#include <cuda_bf16.h>

#define Nb  8
#define Ssz 1024
#define Esz 1024
#define Hn  16
#define DKs 64
#define NSE (Nb*Ssz*Esz)                 // 8388608
#define NSE2 (NSE/2)
#define EE2 (Esz*Esz/2)
#define NHSS (134217728)

// Packed bf16 hi/lo planes (word i = pair (2i, 2i+1) along k)
__device__ unsigned g_Inh[NSE2], g_Inl[NSE2];
__device__ unsigned g_Qh[NSE2], g_Ql[NSE2];
__device__ unsigned g_Kh[NSE2], g_Kl[NSE2];
__device__ unsigned g_Vth[NSE2], g_Vtl[NSE2];      // [nh][d][t/2]
__device__ unsigned g_Oh[NSE2], g_Ol[NSE2];
__device__ unsigned g_Wth[4*EE2], g_Wtl[4*EE2];
__device__ float    g_Vt[NSE];
__device__ float2   g_stats[Hn*Nb*Ssz];            // per (nh,row): {rowmax, 1/sum}
__device__ float    g_attn_fb[NHSS];

#define CPA16(saddr, gptr) asm volatile("cp.async.cg.shared.global [%0], [%1], 16;\n" :: "r"(saddr), "l"(gptr))
#define CPCOMMIT() asm volatile("cp.async.commit_group;\n")
#define CPWAIT(n)  asm volatile("cp.async.wait_group %0;\n" :: "n"(n))

__device__ __forceinline__ void pack2(float x, float y, unsigned& h, unsigned& l) {
  __nv_bfloat162 hh = __float22bfloat162_rn(make_float2(x, y));
  float2 f = __bfloat1622float2(hh);
  __nv_bfloat162 ll = __float22bfloat162_rn(make_float2(x - f.x, y - f.y));
  h = *reinterpret_cast<unsigned*>(&hh);
  l = *reinterpret_cast<unsigned*>(&ll);
}

__device__ __forceinline__ void mma4(float* c, const unsigned* a, unsigned b0, unsigned b1) {
  asm volatile(
      "mma.sync.aligned.m16n8k16.row.col.f32.bf16.bf16.f32 "
      "{%0,%1,%2,%3}, {%4,%5,%6,%7}, {%8,%9}, {%0,%1,%2,%3};\n"
      : "+f"(c[0]), "+f"(c[1]), "+f"(c[2]), "+f"(c[3])
      : "r"(a[0]), "r"(a[1]), "r"(a[2]), "r"(a[3]), "r"(b0), "r"(b1));
}

template <int MT, int NT, int PITCH, int CH>
__device__ __forceinline__ void compute_tile2(
    const unsigned* Ah, const unsigned* Al, const unsigned* Bh, const unsigned* Bl,
    int wm0, int wn0, int gr, int q, float (&acc)[MT][NT][4]) {
#pragma unroll
  for (int c = 0; c < CH; c++) {
    unsigned ah[MT][4], al[MT][4];
#pragma unroll
    for (int mt = 0; mt < MT; mt++) {
      int r0 = (wm0 + 16*mt + gr)*PITCH + 8*c + q;
      int r1 = (wm0 + 16*mt + 8 + gr)*PITCH + 8*c + q;
      ah[mt][0]=Ah[r0]; ah[mt][1]=Ah[r1]; ah[mt][2]=Ah[r0+4]; ah[mt][3]=Ah[r1+4];
      al[mt][0]=Al[r0]; al[mt][1]=Al[r1]; al[mt][2]=Al[r0+4]; al[mt][3]=Al[r1+4];
    }
#pragma unroll
    for (int nt = 0; nt < NT; nt++) {
      int rb = (wn0 + 8*nt + gr)*PITCH + 8*c + q;
      unsigned bh0=Bh[rb], bh1=Bh[rb+4], bl0=Bl[rb], bl1=Bl[rb+4];
#pragma unroll
      for (int mt = 0; mt < MT; mt++) {
        mma4(acc[mt][nt], ah[mt], bh0, bh1);
        mma4(acc[mt][nt], ah[mt], bl0, bl1);
        mma4(acc[mt][nt], al[mt], bh0, bh1);
      }
    }
  }
}

__global__ void convert_pack(const float* __restrict__ src,
                             unsigned* __restrict__ h, unsigned* __restrict__ l, int npairs) {
  for (int i = blockIdx.x*blockDim.x + threadIdx.x; i < npairs; i += gridDim.x*blockDim.x) {
    float2 v = ((const float2*)src)[i];
    pack2(v.x, v.y, h[i], l[i]);
  }
}

__global__ __launch_bounds__(256) void transpose_convert(
    const float* __restrict__ W, unsigned* __restrict__ Th, unsigned* __restrict__ Tl) {
  __shared__ float tile[32][33];
  int bx = blockIdx.x*32, by = blockIdx.y*32;
  int t = threadIdx.x, x = t & 31, y = t >> 5;
#pragma unroll
  for (int i = 0; i < 4; i++)
    tile[y + 8*i][x] = W[(size_t)(by + y + 8*i)*1024 + bx + x];
  __syncthreads();
#pragma unroll
  for (int j = 0; j < 2; j++) {
    int idx = t + 256*j;
    int n = idx >> 4, p = idx & 15;
    unsigned h, l;
    pack2(tile[2*p][n], tile[2*p+1][n], h, l);
    Th[(size_t)(bx + n)*512 + (by >> 1) + p] = h;
    Tl[(size_t)(bx + n)*512 + (by >> 1) + p] = l;
  }
}

__device__ __forceinline__ void proj_issue(
    unsigned sbase, const unsigned* Ah_g, const unsigned* Al_g,
    const unsigned* Bh_g, const unsigned* Bl_g, int m0, int n0, int kt2, int tid) {
#pragma unroll
  for (int j = 0; j < 2; j++) {
    int c = tid + 256*j;
    int m = c >> 2, kc = c & 3;
    unsigned d = sbase + (unsigned)((m*20 + kc*4)*4);
    size_t ga = (size_t)m*512 + kt2 + kc*4;
    CPA16(d + 0u*10240u, Ah_g + (size_t)m0*512 + ga);
    CPA16(d + 1u*10240u, Al_g + (size_t)m0*512 + ga);
    CPA16(d + 2u*10240u, Bh_g + (size_t)n0*512 + ga);
    CPA16(d + 3u*10240u, Bl_g + (size_t)n0*512 + ga);
  }
}

// ---------------------------------------------------------------------------
// Projection GEMM from planes. EPI: 0=write planes, 1=write fp32, 2=write Vt fp32
// ---------------------------------------------------------------------------
template <int EPI>
__global__ __launch_bounds__(256, 2) void proj_mma(
    const unsigned* __restrict__ Ah_g, const unsigned* __restrict__ Al_g,
    const unsigned* __restrict__ Bh_g, const unsigned* __restrict__ Bl_g,
    const float* __restrict__ bias, float* __restrict__ Cf,
    unsigned* __restrict__ Ch, unsigned* __restrict__ Cl) {
  extern __shared__ unsigned sm[];
  const int tid = threadIdx.x, wid = tid >> 5, lane = tid & 31;
  const int gr = lane >> 2, q = lane & 3;
  const int wm0 = (wid >> 2)*64, wn0 = (wid & 3)*32;
  const int m0 = blockIdx.y*128, n0 = blockIdx.x*128;
  unsigned smu = (unsigned)__cvta_generic_to_shared(sm);
  float acc[4][4][4] = {};
  proj_issue(smu, Ah_g, Al_g, Bh_g, Bl_g, m0, n0, 0, tid);
  CPCOMMIT();
  for (int t = 0; t < 32; t++) {
    if (t + 1 < 32)
      proj_issue(smu + ((t+1)&1)*40960u, Ah_g, Al_g, Bh_g, Bl_g, m0, n0, (t+1)*16, tid);
    CPCOMMIT();
    CPWAIT(1);
    __syncthreads();
    const unsigned* base = sm + (t&1)*10240;
    compute_tile2<4,4,20,2>(base, base+2560, base+5120, base+7680, wm0, wn0, gr, q, acc);
    __syncthreads();
  }
#pragma unroll
  for (int mt = 0; mt < 4; mt++) {
#pragma unroll
    for (int nt = 0; nt < 4; nt++) {
      int row = m0 + wm0 + 16*mt + gr;
      int col = n0 + wn0 + 8*nt + 2*q;
      float b0 = bias[col], b1 = bias[col+1];
      float v0 = acc[mt][nt][0] + b0, v1 = acc[mt][nt][1] + b1;
      float v2 = acc[mt][nt][2] + b0, v3 = acc[mt][nt][3] + b1;
      if (EPI == 0) {
        int w = col >> 1;
        pack2(v0, v1, Ch[(size_t)row*512 + w], Cl[(size_t)row*512 + w]);
        pack2(v2, v3, Ch[(size_t)(row+8)*512 + w], Cl[(size_t)(row+8)*512 + w]);
      } else if (EPI == 1) {
        *(float2*)&Cf[(size_t)row*1024 + col] = make_float2(v0, v1);
        *(float2*)&Cf[(size_t)(row+8)*1024 + col] = make_float2(v2, v3);
      } else {
        int nb = row >> 10, s = row & 1023;
        int h = col >> 6, d = col & 63;
        float* p = Cf + (((size_t)(nb*16 + h))*64 + d)*1024 + s;
        p[0] = v0; p[1024] = v1; p[8] = v2; p[1024 + 8] = v3;
      }
    }
  }
}

__device__ __forceinline__ void comb(float& m, float& s, float m2, float s2) {
  float M = fmaxf(m, m2);
  s = s*__expf(m - M) + s2*__expf(m2 - M);
  m = M;
}

// ---------------------------------------------------------------------------
// QK^T + online row stats. One CTA = 128 rows x full 1024 cols of one head.
// Warps tile 16 rows x 128 cols. Writes masked/scaled logits + (max, 1/sum).
// smem: Qh(4608) Ql(4608) | B double buffer 2x(Bh 4608, Bl 4608). 110592 B.
// ---------------------------------------------------------------------------
__global__ __launch_bounds__(256) void qk_stats_mma(
    const int* __restrict__ mask, float* __restrict__ attn) {
  extern __shared__ unsigned sm[];
  const int tid = threadIdx.x, wid = tid >> 5, lane = tid & 31;
  const int gr = lane >> 2, q = lane & 3;
  const int wm0 = wid*16;
  const int m0 = blockIdx.x*128;
  const int nh = blockIdx.y, nb = nh >> 4, h = nh & 15;
  unsigned smu = (unsigned)__cvta_generic_to_shared(sm);
  const size_t qoff = (size_t)(nb*1024 + m0)*512 + h*32;
  const size_t koff0 = (size_t)(nb*1024)*512 + h*32;

  // Q load (group 0)
#pragma unroll
  for (int j = 0; j < 4; j++) {
    int c = tid + 256*j;
    int m = c >> 3, kc = c & 7;
    unsigned d = smu + (unsigned)((m*36 + kc*4)*4);
    size_t ga = (size_t)m*512 + kc*4;
    CPA16(d, g_Qh + qoff + ga);
    CPA16(d + 18432u, g_Ql + qoff + ga);
  }
  CPCOMMIT();
  // B tile 0
#pragma unroll
  for (int j = 0; j < 4; j++) {
    int c = tid + 256*j;
    int m = c >> 3, kc = c & 7;
    unsigned d = smu + 36864u + (unsigned)((m*36 + kc*4)*4);
    size_t ga = (size_t)m*512 + kc*4;
    CPA16(d, g_Kh + koff0 + ga);
    CPA16(d + 18432u, g_Kl + koff0 + ga);
  }
  CPCOMMIT();

  float m0r = -1e30f, s0r = 0.f, m1r = -1e30f, s1r = 0.f;
  const int row0 = m0 + wm0 + gr;

  for (int t = 0; t < 8; t++) {
    if (t + 1 < 8) {
      size_t koff = koff0 + (size_t)(t+1)*128*512;
#pragma unroll
      for (int j = 0; j < 4; j++) {
        int c = tid + 256*j;
        int m = c >> 3, kc = c & 7;
        unsigned d = smu + 36864u + ((t+1)&1)*36864u + (unsigned)((m*36 + kc*4)*4);
        size_t ga = (size_t)m*512 + kc*4;
        CPA16(d, g_Kh + koff + ga);
        CPA16(d + 18432u, g_Kl + koff + ga);
      }
    }
    CPCOMMIT();
    CPWAIT(1);
    __syncthreads();
    float acc[1][16][4] = {};
    const unsigned* B = sm + 9216 + (t&1)*9216;
    compute_tile2<1,16,36,4>(sm, sm + 4608, B, B + 4608, wm0, 0, gr, q, acc);
    __syncthreads();

    // mask + scale + store logits; keep masked vals in acc
    int t0 = t*128;
#pragma unroll
    for (int nt = 0; nt < 16; nt++) {
      int col = t0 + 8*nt + 2*q;
      int2 mA = *(const int2*)&mask[(size_t)(nb*1024 + row0)*1024 + col];
      int2 mB = *(const int2*)&mask[(size_t)(nb*1024 + row0 + 8)*1024 + col];
      float v0 = mA.x ? -1e9f : acc[0][nt][0]*0.125f;
      float v1 = mA.y ? -1e9f : acc[0][nt][1]*0.125f;
      float v2 = mB.x ? -1e9f : acc[0][nt][2]*0.125f;
      float v3 = mB.y ? -1e9f : acc[0][nt][3]*0.125f;
      *(float2*)&attn[((size_t)nh*1024 + row0)*1024 + col] = make_float2(v0, v1);
      *(float2*)&attn[((size_t)nh*1024 + row0 + 8)*1024 + col] = make_float2(v2, v3);
      acc[0][nt][0]=v0; acc[0][nt][1]=v1; acc[0][nt][2]=v2; acc[0][nt][3]=v3;
    }
    // online stats update
    float tm0 = -1e30f, tm1 = -1e30f;
#pragma unroll
    for (int nt = 0; nt < 16; nt++) {
      tm0 = fmaxf(tm0, fmaxf(acc[0][nt][0], acc[0][nt][1]));
      tm1 = fmaxf(tm1, fmaxf(acc[0][nt][2], acc[0][nt][3]));
    }
    float nm0 = fmaxf(m0r, tm0), nm1 = fmaxf(m1r, tm1);
    s0r *= __expf(m0r - nm0); s1r *= __expf(m1r - nm1);
    m0r = nm0; m1r = nm1;
#pragma unroll
    for (int nt = 0; nt < 16; nt++) {
      s0r += __expf(acc[0][nt][0] - m0r) + __expf(acc[0][nt][1] - m0r);
      s1r += __expf(acc[0][nt][2] - m1r) + __expf(acc[0][nt][3] - m1r);
    }
  }
  // reduce across the 4 lanes of the quad (bits 0,1 of lane)
#pragma unroll
  for (int off = 1; off <= 2; off <<= 1) {
    float mm = __shfl_xor_sync(0xffffffffu, m0r, off);
    float ss = __shfl_xor_sync(0xffffffffu, s0r, off);
    comb(m0r, s0r, mm, ss);
    mm = __shfl_xor_sync(0xffffffffu, m1r, off);
    ss = __shfl_xor_sync(0xffffffffu, s1r, off);
    comb(m1r, s1r, mm, ss);
  }
  if (q == 0) {
    g_stats[(size_t)nh*1024 + row0]     = make_float2(m0r, 1.0f/s0r);
    g_stats[(size_t)nh*1024 + row0 + 8] = make_float2(m1r, 1.0f/s1r);
  }
}

// ---------------------------------------------------------------------------
// Fused normalize + PV. Reads logits, computes p = exp(x-m)/s, writes p back
// in place (attn output), splits p for the MMA against Vt planes. Writes O planes.
// ---------------------------------------------------------------------------
__global__ __launch_bounds__(256, 2) void pv_mma(float* __restrict__ attn) {
  __shared__ unsigned Ah[2560], Al[2560], Bh[1280], Bl[1280];
  const int tid = threadIdx.x, wid = tid >> 5, lane = tid & 31;
  const int gr = lane >> 2, q = lane & 3;
  const int wm0 = (wid >> 2)*64, wn0 = (wid & 3)*16;
  const int m0 = blockIdx.x*128;
  const int nh = blockIdx.y, nb = nh >> 4, h = nh & 15;
  float* P = attn + (size_t)nh*1024*1024 + (size_t)m0*1024;
  // preload stats for the 4 rows this thread loads
  float2 st[4];
#pragma unroll
  for (int j = 0; j < 4; j++)
    st[j] = g_stats[(size_t)nh*1024 + m0 + (tid >> 3) + 32*j];
  float acc[4][2][4] = {};
  for (int kt = 0; kt < 1024; kt += 32) {
#pragma unroll
    for (int j = 0; j < 4; j++) {
      int e = tid + 256*j;
      int m = e >> 3, kq = e & 7;
      float* gp = P + (size_t)m*1024 + kt + 4*kq;
      float4 v = *(const float4*)gp;
      float mm = st[j].x, inv = st[j].y;
      float4 p;
      p.x = __expf(v.x - mm)*inv; p.y = __expf(v.y - mm)*inv;
      p.z = __expf(v.z - mm)*inv; p.w = __expf(v.w - mm)*inv;
      *(float4*)gp = p;
      unsigned h01, h23, l01, l23;
      pack2(p.x, p.y, h01, l01);
      pack2(p.z, p.w, h23, l23);
      int base = m*20 + 2*kq;
      Ah[base]=h01; Ah[base+1]=h23; Al[base]=l01; Al[base+1]=l23;
    }
    {
      int m = tid >> 2, kc = tid & 3;
      if (m < 64) {
        size_t src = (size_t)(nh*64 + m)*512 + (kt >> 1) + kc*4;
        *(uint4*)&Bh[m*20 + kc*4] = *(const uint4*)&g_Vth[src];
        *(uint4*)&Bl[m*20 + kc*4] = *(const uint4*)&g_Vtl[src];
      }
    }
    __syncthreads();
    compute_tile2<4,2,20,2>(Ah, Al, Bh, Bl, wm0, wn0, gr, q, acc);
    __syncthreads();
  }
#pragma unroll
  for (int mt = 0; mt < 4; mt++) {
#pragma unroll
    for (int nt = 0; nt < 2; nt++) {
      int s = m0 + wm0 + 16*mt + gr;
      int col = h*64 + wn0 + 8*nt + 2*q;
      int w = col >> 1;
      size_t r0 = (size_t)(nb*1024 + s)*512 + w;
      size_t r1 = (size_t)(nb*1024 + s + 8)*512 + w;
      pack2(acc[mt][nt][0], acc[mt][nt][1], g_Oh[r0], g_Ol[r0]);
      pack2(acc[mt][nt][2], acc[mt][nt][3], g_Oh[r1], g_Ol[r1]);
    }
  }
}

// ---------------------------------------------------------------------------
extern "C" void kernel_launch(void* const* d_in, const int* in_sizes, int n_in,
                              void* d_out, int out_size) {
  const float* q  = (const float*)d_in[0];
  const float* k  = (const float*)d_in[1];
  const float* v  = (const float*)d_in[2];
  const int*   mask = (const int*)d_in[3];
  const float* wq = (const float*)d_in[4];
  const float* bq = (const float*)d_in[5];
  const float* wk = (const float*)d_in[6];
  const float* bk = (const float*)d_in[7];
  const float* wv = (const float*)d_in[8];
  const float* bv = (const float*)d_in[9];
  const float* wo = (const float*)d_in[10];
  const float* bo = (const float*)d_in[11];
  float* out = (float*)d_out;

  static bool attr_done = false;
  if (!attr_done) {
    cudaFuncSetAttribute(proj_mma<0>, cudaFuncAttributeMaxDynamicSharedMemorySize, 81920);
    cudaFuncSetAttribute(proj_mma<1>, cudaFuncAttributeMaxDynamicSharedMemorySize, 81920);
    cudaFuncSetAttribute(proj_mma<2>, cudaFuncAttributeMaxDynamicSharedMemorySize, 81920);
    cudaFuncSetAttribute(qk_stats_mma, cudaFuncAttributeMaxDynamicSharedMemorySize, 110592);
    attr_done = true;
  }

  unsigned *Inh, *Inl, *Qh, *Ql, *Kh, *Kl, *Vth, *Vtl, *Oh, *Ol, *Wth, *Wtl;
  float *Vtp, *attn;
  cudaGetSymbolAddress((void**)&Inh, g_Inh);  cudaGetSymbolAddress((void**)&Inl, g_Inl);
  cudaGetSymbolAddress((void**)&Qh, g_Qh);    cudaGetSymbolAddress((void**)&Ql, g_Ql);
  cudaGetSymbolAddress((void**)&Kh, g_Kh);    cudaGetSymbolAddress((void**)&Kl, g_Kl);
  cudaGetSymbolAddress((void**)&Vth, g_Vth);  cudaGetSymbolAddress((void**)&Vtl, g_Vtl);
  cudaGetSymbolAddress((void**)&Oh, g_Oh);    cudaGetSymbolAddress((void**)&Ol, g_Ol);
  cudaGetSymbolAddress((void**)&Wth, g_Wth);  cudaGetSymbolAddress((void**)&Wtl, g_Wtl);
  cudaGetSymbolAddress((void**)&Vtp, g_Vt);
  if ((long long)out_size >= (long long)NSE + (long long)NHSS) {
    attn = out + NSE;
  } else {
    cudaGetSymbolAddress((void**)&attn, g_attn_fb);
  }

  dim3 tg(32, 32);
  transpose_convert<<<tg, 256>>>(wq, Wth + 0*EE2, Wtl + 0*EE2);
  transpose_convert<<<tg, 256>>>(wk, Wth + 1*EE2, Wtl + 1*EE2);
  transpose_convert<<<tg, 256>>>(wv, Wth + 2*EE2, Wtl + 2*EE2);
  transpose_convert<<<tg, 256>>>(wo, Wth + 3*EE2, Wtl + 3*EE2);

  dim3 gp(8, 64);
  convert_pack<<<2048, 256>>>(q, Inh, Inl, NSE2);
  proj_mma<0><<<gp, 256, 81920>>>(Inh, Inl, Wth + 0*EE2, Wtl + 0*EE2, bq, nullptr, Qh, Ql);
  convert_pack<<<2048, 256>>>(k, Inh, Inl, NSE2);
  proj_mma<0><<<gp, 256, 81920>>>(Inh, Inl, Wth + 1*EE2, Wtl + 1*EE2, bk, nullptr, Kh, Kl);
  convert_pack<<<2048, 256>>>(v, Inh, Inl, NSE2);
  proj_mma<2><<<gp, 256, 81920>>>(Inh, Inl, Wth + 2*EE2, Wtl + 2*EE2, bv, Vtp, nullptr, nullptr);
  convert_pack<<<2048, 256>>>(Vtp, Vth, Vtl, NSE2);

  qk_stats_mma<<<dim3(8, 128), 256, 110592>>>(mask, attn);
  pv_mma<<<dim3(8, 128), 256>>>(attn);
  proj_mma<1><<<gp, 256, 81920>>>(Oh, Ol, Wth + 3*EE2, Wtl + 3*EE2, bo, out, nullptr, nullptr);
}